// round 16
// baseline (speedup 1.0000x reference)
#include <cuda_runtime.h>
#include <math.h>

#define BB   4
#define CIN  512
#define COUT 128
#define SLOTPAD 270848   // BB*COUT*529

typedef unsigned long long u64;

__device__ __forceinline__ u64 pk2(float lo, float hi) {
    u64 r; asm("mov.b64 %0, {%1, %2};" : "=l"(r) : "f"(lo), "f"(hi)); return r;
}
__device__ __forceinline__ void upk2(u64 v, float& lo, float& hi) {
    asm("mov.b64 {%0, %1}, %2;" : "=f"(lo), "=f"(hi) : "l"(v));
}
__device__ __forceinline__ void fma2(u64& d, u64 a, u64 b) {
    asm("fma.rn.f32x2 %0, %1, %2, %0;" : "+l"(d) : "l"(a), "l"(b));
}

// ---------------- static device scratch ----------------
__device__ float g_interp[2][1855488];
__device__ float g_part[4][6 * SLOTPAD];
__device__ float g_feat[6][SLOTPAD];
__device__ float g_norm[6][BB*529];
__device__ float g_pair[9][BB*529*529];
__device__ float g_corr6d[BB*9*65536];
__device__ float g_conv6d[BB*9*65536];
__device__ float g_max4[BB*65536];
__device__ float g_i32[(size_t)BB*1048576];
__device__ float g_c2d[(size_t)BB*1048576];
__device__ float g_cmax[BB*1024];
__device__ float g_attn[(size_t)BB*1048576];
__device__ float g_wT[3][CIN*9*COUT];

__device__ __forceinline__ void axisw(int o, float sc, int hi,
                                      int& i0, int& i1, float& w) {
    float f = (float)o * sc;
    int a = (int)f;
    if (a > hi) a = hi;
    w  = f - (float)a;
    i0 = a;
    i1 = (a + 1 < hi) ? a + 1 : hi;
}

// ---------------- 0) weight transpose [oc][ic*9] -> [ic*9][oc] ----------------
__global__ void wtrans_kernel(const float* __restrict__ w0,
                              const float* __restrict__ w1,
                              const float* __restrict__ w2) {
    int s = blockIdx.y;
    const float* w = (s == 0) ? w0 : ((s == 1) ? w1 : w2);
    int i = blockIdx.x * 256 + threadIdx.x;
    if (i >= COUT * CIN * 9) return;
    int oc = i / (CIN * 9);
    int r  = i % (CIN * 9);
    g_wT[s][(size_t)r * COUT + oc] = w[i];
}

// ---------------- 1) bilinear 16x16 -> sz x sz ----------------
__global__ void interp_feat_kernel(const float* __restrict__ in, int which) {
    int s = blockIdx.y;
    int sz = (s == 0) ? 11 : ((s == 1) ? 16 : 23);
    int off = (s == 0) ? 0 : ((s == 1) ? 247808 : 772096);
    int idx = blockIdx.x * 256 + threadIdx.x;
    int total = BB * CIN * sz * sz;
    if (idx >= total) return;
    int x  = idx % sz;
    int y  = (idx / sz) % sz;
    int bc = idx / (sz * sz);
    float sc = 15.0f / (float)(sz - 1);
    int y0, y1, x0, x1; float wy, wx;
    axisw(y, sc, 15, y0, y1, wy);
    axisw(x, sc, 15, x0, x1, wx);
    const float* p = in + (size_t)bc * 256;
    float v = (1.f - wy) * ((1.f - wx) * p[y0*16 + x0] + wx * p[y0*16 + x1])
            +        wy  * ((1.f - wx) * p[y1*16 + x0] + wx * p[y1*16 + x1]);
    g_interp[which][off + idx] = v;
}

// ---------------- 2) 3x3 conv 512->128 as f32x2 GEMM, ic split 4 ways ----------------
__global__ __launch_bounds__(256) void conv2d_kernel() {
    int t = blockIdx.x;   // 0..14
    int s, tile;
    if (t < 2)      { s = 0; tile = t; }
    else if (t < 6) { s = 1; tile = t - 2; }
    else            { s = 2; tile = t - 6; }
    int sz  = (s == 0) ? 11 : ((s == 1) ? 16 : 23);
    int off = (s == 0) ? 0  : ((s == 1) ? 247808 : 772096);
    int n2  = sz * sz;
    int which = blockIdx.y & 1;
    int b     = blockIdx.y >> 1;
    int chunk = blockIdx.z;
    int px0 = tile * 64;

    __shared__ __align__(16) float Ws[36 * 128];
    __shared__ __align__(16) float Xs[36 * 64];

    int tid = threadIdx.x;
    int ocg = tid >> 4;
    int pxg = tid & 15;

    int jj = tid & 63;
    int gg = tid >> 6;
    int gpx = px0 + jj;
    bool gvalid = (gpx < n2);
    int gy = 0, gx = 0;
    if (gvalid) { gy = gpx / sz; gx = gpx - gy * sz; }

    const float* inb = g_interp[which] + off + (size_t)b * CIN * n2;
    const float* wT  = g_wT[s];

    u64 acc[4][4];
#pragma unroll
    for (int i = 0; i < 4; i++)
#pragma unroll
        for (int j = 0; j < 4; j++) acc[i][j] = 0ull;

    int icBeg = chunk * 128;
    for (int ic0 = icBeg; ic0 < icBeg + 128; ic0 += 4) {
        const float* wsrc = wT + (size_t)(ic0 * 9) * COUT;
#pragma unroll
        for (int l = 0; l < 18; l++)
            Ws[tid + l * 256] = wsrc[tid + l * 256];
        {
            const float* ib = inb + (size_t)(ic0 + gg) * n2;
#pragma unroll
            for (int kk = 0; kk < 9; kk++) {
                int ky = kk / 3, kx = kk % 3;
                int yy = gy + ky - 1, xx = gx + kx - 1;
                float v = 0.f;
                if (gvalid && (unsigned)yy < (unsigned)sz && (unsigned)xx < (unsigned)sz)
                    v = ib[yy * sz + xx];
                Xs[(gg * 9 + kk) * 64 + jj] = v;
            }
        }
        __syncthreads();
#pragma unroll 6
        for (int r = 0; r < 36; r++) {
            const u64* wr = (const u64*)(Ws + r * 128) + ocg * 4;
            u64 w4[4];
            w4[0] = wr[0]; w4[1] = wr[1]; w4[2] = wr[2]; w4[3] = wr[3];
            const float* xr = Xs + r * 64 + pxg * 4;
            u64 xp[4];
#pragma unroll
            for (int i2 = 0; i2 < 4; i2++) { float xv = xr[i2]; xp[i2] = pk2(xv, xv); }
#pragma unroll
            for (int p2 = 0; p2 < 4; p2++)
#pragma unroll
                for (int i2 = 0; i2 < 4; i2++)
                    fma2(acc[p2][i2], w4[p2], xp[i2]);
        }
        __syncthreads();
    }

    int oc0 = ocg * 8;
    int slot = which * 3 + s;
    float* outp = g_part[chunk] + (size_t)slot * SLOTPAD + (size_t)b * COUT * n2;
#pragma unroll
    for (int p2 = 0; p2 < 4; p2++)
#pragma unroll
        for (int i2 = 0; i2 < 4; i2++) {
            float lo, hi;
            upk2(acc[p2][i2], lo, hi);
            int px = px0 + pxg * 4 + i2;
            if (px < n2) {
                outp[(size_t)(oc0 + 2*p2)     * n2 + px] = lo;
                outp[(size_t)(oc0 + 2*p2 + 1) * n2 + px] = hi;
            }
        }
}

// ---------------- 2b) reduce the 4 ic-chunks ----------------
__global__ void reduce4_kernel() {
    size_t i = (size_t)blockIdx.x * 256 + threadIdx.x;
    if (i >= (size_t)6 * SLOTPAD) return;
    (&g_feat[0][0])[i] = g_part[0][i] + g_part[1][i] + g_part[2][i] + g_part[3][i];
}

// ---------------- 3) per-pixel channel norms ----------------
__global__ void norm_kernel() {
    int slot = blockIdx.y;
    int s = slot % 3;
    int n2 = (s == 0) ? 121 : ((s == 1) ? 256 : 529);
    int rows = BB * n2;
    int wrp = blockIdx.x * 8 + (threadIdx.x >> 5);
    int lane = threadIdx.x & 31;
    if (wrp >= rows) return;
    int b = wrp / n2, n = wrp - b * n2;
    const float* f = g_feat[slot] + (size_t)b * COUT * n2 + n;
    float ssum = 0.f;
#pragma unroll
    for (int k = 0; k < 4; k++) {
        float v = f[(size_t)(lane + 32 * k) * n2];
        ssum += v * v;
    }
#pragma unroll
    for (int o = 16; o > 0; o >>= 1) ssum += __shfl_xor_sync(0xffffffffu, ssum, o);
    if (lane == 0) g_norm[slot][wrp] = sqrtf(ssum);
}

// ---------------- 4) normalized correlation GEMM, all 9 pairs fused ----------------
__global__ __launch_bounds__(256) void corr_kernel() {
    __shared__ float Ss[16][17];
    __shared__ float Ts[16][17];
    int z = blockIdx.z;
    int pair = z % 9, b = z / 9;
    int si = pair / 3, tj = pair % 3;
    int N = (si == 0) ? 121 : ((si == 1) ? 256 : 529);
    int M = (tj == 0) ? 121 : ((tj == 1) ? 256 : 529);
    int n0 = blockIdx.y * 16, m0 = blockIdx.x * 16;
    if (n0 >= N || m0 >= M) return;
    int tx = threadIdx.x, ty = threadIdx.y;
    const float* sp = g_feat[si]     + (size_t)b * COUT * N;
    const float* tp = g_feat[3 + tj] + (size_t)b * COUT * M;
    float acc = 0.f;
    for (int k0 = 0; k0 < COUT; k0 += 16) {
        int n = n0 + tx;
        Ss[ty][tx] = (n < N) ? sp[(size_t)(k0 + ty) * N + n] : 0.f;
        int m = m0 + tx;
        Ts[ty][tx] = (m < M) ? tp[(size_t)(k0 + ty) * M + m] : 0.f;
        __syncthreads();
#pragma unroll
        for (int kk = 0; kk < 16; kk++) acc += Ss[kk][ty] * Ts[kk][tx];
        __syncthreads();
    }
    int n = n0 + ty, m = m0 + tx;
    if (n < N && m < M) {
        float d = g_norm[si][b * N + n] * g_norm[3 + tj][b * M + m];
        g_pair[pair][(size_t)b * N * M + (size_t)n * M + m] = acc / d;
    }
}

// ---------------- 5) 4D tensor-product bilinear to 16^4 + clip, all 9 pairs ----------------
__global__ void interp4d_pair_kernel() {
    int pair = blockIdx.y;
    int si = pair / 3, tj = pair % 3;
    int ssi = (si == 0) ? 11 : ((si == 1) ? 16 : 23);
    int ssj = (tj == 0) ? 11 : ((tj == 1) ? 16 : 23);
    int idx = blockIdx.x * 256 + threadIdx.x;
    if (idx >= BB * 65536) return;
    int b = idx >> 16;
    int r = idx & 65535;
    int x2 = r & 15, y2 = (r >> 4) & 15, x1 = (r >> 8) & 15, y1 = r >> 12;
    float sc1 = (float)(ssi - 1) / 15.0f, sc2 = (float)(ssj - 1) / 15.0f;
    int a0, a1, e0, e1, c0, c1, d0, d1;
    float wa, we, wc, wd;
    axisw(y1, sc1, ssi - 1, a0, a1, wa);
    axisw(x1, sc1, ssi - 1, e0, e1, we);
    axisw(y2, sc2, ssj - 1, c0, c1, wc);
    axisw(x2, sc2, ssj - 1, d0, d1, wd);
    const float* p = g_pair[pair] + (size_t)b * ssi * ssi * ssj * ssj;
    int M = ssj * ssj;
    int AA[2] = {a0, a1}; float WA[2] = {1.f - wa, wa};
    int EE[2] = {e0, e1}; float WE[2] = {1.f - we, we};
    int CC[2] = {c0, c1}; float WC[2] = {1.f - wc, wc};
    int DD[2] = {d0, d1}; float WD[2] = {1.f - wd, wd};
    float v = 0.f;
#pragma unroll
    for (int ii = 0; ii < 2; ii++)
#pragma unroll
        for (int jj = 0; jj < 2; jj++) {
            const float* row = p + (size_t)(AA[ii] * ssi + EE[jj]) * M;
            float inner = WC[0] * (WD[0] * row[CC[0]*ssj + DD[0]] + WD[1] * row[CC[0]*ssj + DD[1]])
                        + WC[1] * (WD[0] * row[CC[1]*ssj + DD[0]] + WD[1] * row[CC[1]*ssj + DD[1]]);
            v += WA[ii] * WE[jj] * inner;
        }
    v = fmaxf(v, 0.f);
    g_corr6d[((size_t)(b * 9 + pair) << 16) + r] = v;
}

// ---------------- 6) 6D conv: dual shifted slabs (aligned pe AND po), dynamic smem ----------------
// dsm layout: skc2 (640 u64, 5120B) | slabA (400*22 fl, 35200B) | slabB (400*18 fl, 28800B)
#define C6_SMEM (5120 + 35200 + 28800)
__global__ __launch_bounds__(256, 3) void conv6d_kernel(const float* __restrict__ k6d) {
    extern __shared__ __align__(16) float dsm[];
    u64*   skc2  = (u64*)dsm;            // 640 u64
    float* slabA = dsm + 1280;           // stride 22 per column
    float* slabB = dsm + 1280 + 8800;    // stride 18 per column
    int z1 = blockIdx.x;
    int p  = blockIdx.y;
    int b  = blockIdx.z;
    int a = p / 3, a2 = p % 3;
    int tid = threadIdx.x;
    int z4 = tid & 15, z3 = tid >> 4;

    u64 acc[8];
#pragma unroll
    for (int q = 0; q < 8; q++) acc[q] = 0ull;

    for (int da = 0; da < 3; da++) {
        int ap = a + da - 1; if ((unsigned)ap >= 3u) continue;
        for (int db = 0; db < 3; db++) {
            int bp = a2 + db - 1; if ((unsigned)bp >= 3u) continue;
            __syncthreads();
            for (int i = tid; i < 625; i += 256) {
                float v = k6d[(da * 3 + db) * 625 + i];
                skc2[i] = pk2(v, v);
            }
            const float* volbase = g_corr6d + (((size_t)b * 9 + ap * 3 + bp) << 16);
            for (int z1p = z1 - 2; z1p <= z1 + 2; z1p++) {
                if ((unsigned)z1p >= 16u) continue;
                int d1 = z1p - z1 + 2;
                const float* src = volbase + ((size_t)z1p << 12);
                __syncthreads();
                // column fill: A[z2]=v_pad[z2] (20), B[j]=v_pad[j+1] (18)
                for (int c = tid; c < 400; c += 256) {
                    int sz3 = c / 20, sz4 = c - sz3 * 20;
                    int z3p = sz3 - 2, z4p = sz4 - 2;
                    float* dA = slabA + c * 22;
                    float* dB = slabB + c * 18;
                    if ((unsigned)z3p < 16u && (unsigned)z4p < 16u) {
                        const float* s2p = src + (z3p << 4) + z4p;
                        float vv[16];
#pragma unroll
                        for (int k = 0; k < 16; k++) vv[k] = s2p[k << 8];
                        dA[0] = 0.f; dA[1] = 0.f;
#pragma unroll
                        for (int k = 0; k < 16; k++) dA[2 + k] = vv[k];
                        dA[18] = 0.f; dA[19] = 0.f;
                        dB[0] = 0.f;
#pragma unroll
                        for (int k = 0; k < 16; k++) dB[1 + k] = vv[k];
                        dB[17] = 0.f;
                    } else {
#pragma unroll
                        for (int k = 0; k < 20; k++) dA[k] = 0.f;
#pragma unroll
                        for (int k = 0; k < 18; k++) dB[k] = 0.f;
                    }
                }
                __syncthreads();
                const u64* kk = skc2 + d1 * 125;
#pragma unroll 1
                for (int d3 = 0; d3 < 5; d3++) {
#pragma unroll 1
                    for (int d4 = 0; d4 < 5; d4++) {
                        int col = (z3 + d3) * 20 + (z4 + d4);
                        const float* spA = slabA + col * 22;
                        const float* spB = slabB + col * 18;
                        u64 pe[10];
#pragma unroll
                        for (int i = 0; i < 10; i++)
                            pe[i] = *(const u64*)(spA + 2 * i);
                        u64 po[9];
#pragma unroll
                        for (int i = 0; i < 9; i++)
                            po[i] = *(const u64*)(spB + 2 * i);
#pragma unroll
                        for (int d2 = 0; d2 < 5; d2++) {
                            u64 w2 = kk[d2 * 25 + d3 * 5 + d4];
                            if (d2 & 1) {
#pragma unroll
                                for (int q = 0; q < 8; q++) fma2(acc[q], w2, po[(d2 >> 1) + q]);
                            } else {
#pragma unroll
                                for (int q = 0; q < 8; q++) fma2(acc[q], w2, pe[(d2 >> 1) + q]);
                            }
                        }
                    }
                }
            }
        }
    }
    float* outp = g_conv6d + ((((size_t)b * 9 + a * 3 + a2) * 16 + z1) << 12);
#pragma unroll
    for (int q = 0; q < 8; q++) {
        float lo, hi;
        upk2(acc[q], lo, hi);
        outp[((2*q)   << 8) + (z3 << 4) + z4] = lo;
        outp[((2*q+1) << 8) + (z3 << 4) + z4] = hi;
    }
}

// ---------------- 7) max over 9, +bias, sigmoid ----------------
__global__ void sigmax_kernel(const float* __restrict__ b6) {
    int idx = blockIdx.x * 256 + threadIdx.x;
    if (idx >= BB * 65536) return;
    int b = idx >> 16; int r = idx & 65535;
    const float* p = g_conv6d + (((size_t)b * 9) << 16) + r;
    float m = p[0];
#pragma unroll
    for (int q = 1; q < 9; q++) m = fmaxf(m, p[(size_t)q << 16]);
    m += b6[0];
    g_max4[idx] = 1.f / (1.f + expf(-m));
}

// ---------------- 8) 4D bilinear 16^4 -> 32^4 ----------------
__global__ void up4d_kernel() {
    size_t idx = (size_t)blockIdx.x * 256 + threadIdx.x;
    if (idx >= (size_t)BB * 1048576) return;
    int b = (int)(idx >> 20);
    int r = (int)(idx & 1048575);
    int x2 = r & 31, y2 = (r >> 5) & 31, x1 = (r >> 10) & 31, y1 = r >> 15;
    const float sc = 15.0f / 31.0f;
    int a0, a1, e0, e1, c0, c1, d0, d1; float wa, we, wc, wd;
    axisw(y1, sc, 15, a0, a1, wa);
    axisw(x1, sc, 15, e0, e1, we);
    axisw(y2, sc, 15, c0, c1, wc);
    axisw(x2, sc, 15, d0, d1, wd);
    const float* p = g_max4 + ((size_t)b << 16);
    int AA[2] = {a0, a1}; float WA[2] = {1.f - wa, wa};
    int EE[2] = {e0, e1}; float WE[2] = {1.f - we, we};
    int CC[2] = {c0, c1}; float WC[2] = {1.f - wc, wc};
    int DD[2] = {d0, d1}; float WD[2] = {1.f - wd, wd};
    float v = 0.f;
#pragma unroll
    for (int ii = 0; ii < 2; ii++)
#pragma unroll
        for (int jj = 0; jj < 2; jj++) {
            const float* row = p + ((AA[ii] * 16 + EE[jj]) << 8);
            float inner = WC[0] * (WD[0] * row[(CC[0] << 4) + DD[0]] + WD[1] * row[(CC[0] << 4) + DD[1]])
                        + WC[1] * (WD[0] * row[(CC[1] << 4) + DD[0]] + WD[1] * row[(CC[1] << 4) + DD[1]]);
            v += WA[ii] * WE[jj] * inner;
        }
    g_i32[idx] = v;
}

// ---------------- 9) 4D conv 5^4, i1-paired + f32x2, column fill ----------------
__global__ __launch_bounds__(1024) void conv4d_kernel(const float* __restrict__ k4d,
                                                      const float* __restrict__ b4d) {
    __shared__ float skc[640];
    __shared__ float slab[10368];     // 8*36*36, [s2*1296 + s3*36 + s4]
    int c2  = blockIdx.x;
    int i1a = blockIdx.y * 2;
    int b   = blockIdx.z;
    int tid = threadIdx.x;
    int i4 = tid & 31, i3 = tid >> 5;

    for (int i = tid; i < 625; i += 1024) skc[i] = k4d[i];

    u64 accA[2], accB[2];
#pragma unroll
    for (int q = 0; q < 2; q++) { accA[q] = 0ull; accB[q] = 0ull; }

    const float* base = g_i32 + ((size_t)b << 20);
    for (int i1p = i1a - 2; i1p <= i1a + 3; i1p++) {
        if ((unsigned)i1p >= 32u) continue;
        int d1a = i1p - i1a + 2;
        int d1b = d1a - 1;
        bool va = (unsigned)d1a < 5u;
        bool vb = (unsigned)d1b < 5u;
        const float* src = base + ((size_t)i1p << 15);
        __syncthreads();
        for (int c = tid; c < 1296; c += 1024) {
            int s3 = c / 36, s4 = c - s3 * 36;
            int i3p = s3 - 2, i4p = s4 - 2;
            bool v34 = ((unsigned)i3p < 32u) && ((unsigned)i4p < 32u);
            const float* sp2 = src + (i3p << 5) + i4p;
#pragma unroll
            for (int s2 = 0; s2 < 8; s2++) {
                int i2p = c2 * 4 + s2 - 2;
                float vv = 0.f;
                if (v34 && (unsigned)i2p < 32u) vv = sp2[(size_t)i2p << 10];
                slab[s2 * 1296 + c] = vv;
            }
        }
        __syncthreads();
        const float* kA = skc + d1a * 125;
        const float* kB = skc + d1b * 125;
#pragma unroll 1
        for (int d3 = 0; d3 < 5; d3++) {
#pragma unroll 1
            for (int d4 = 0; d4 < 5; d4++) {
                float pvz[8];
                const float* sp = slab + (i3 + d3) * 36 + (i4 + d4);
#pragma unroll
                for (int s = 0; s < 8; s++) pvz[s] = sp[s * 1296];
                u64 pe[4], po[3];
#pragma unroll
                for (int i = 0; i < 4; i++) pe[i] = pk2(pvz[2*i], pvz[2*i+1]);
#pragma unroll
                for (int i = 0; i < 3; i++) po[i] = pk2(pvz[2*i+1], pvz[2*i+2]);
                if (va) {
#pragma unroll
                    for (int d2 = 0; d2 < 5; d2++) {
                        float w = kA[d2 * 25 + d3 * 5 + d4];
                        u64 w2 = pk2(w, w);
                        if (d2 & 1) {
#pragma unroll
                            for (int q = 0; q < 2; q++) fma2(accA[q], w2, po[(d2 >> 1) + q]);
                        } else {
#pragma unroll
                            for (int q = 0; q < 2; q++) fma2(accA[q], w2, pe[(d2 >> 1) + q]);
                        }
                    }
                }
                if (vb) {
#pragma unroll
                    for (int d2 = 0; d2 < 5; d2++) {
                        float w = kB[d2 * 25 + d3 * 5 + d4];
                        u64 w2 = pk2(w, w);
                        if (d2 & 1) {
#pragma unroll
                            for (int q = 0; q < 2; q++) fma2(accB[q], w2, po[(d2 >> 1) + q]);
                        } else {
#pragma unroll
                            for (int q = 0; q < 2; q++) fma2(accB[q], w2, pe[(d2 >> 1) + q]);
                        }
                    }
                }
            }
        }
    }
    float bb = b4d[0];
    size_t obase = ((size_t)b << 20) + i3 * 32 + i4;
#pragma unroll
    for (int q = 0; q < 2; q++) {
        float lo, hi;
        upk2(accA[q], lo, hi);
        float x0 = lo + bb, x1 = hi + bb;
        g_c2d[obase + ((size_t)(i1a * 32 + c2 * 4 + 2*q)     << 10)] =
            fmaxf(x0, 0.f) + log1pf(expf(-fabsf(x0)));
        g_c2d[obase + ((size_t)(i1a * 32 + c2 * 4 + 2*q + 1) << 10)] =
            fmaxf(x1, 0.f) + log1pf(expf(-fabsf(x1)));
        upk2(accB[q], lo, hi);
        x0 = lo + bb; x1 = hi + bb;
        g_c2d[obase + ((size_t)((i1a + 1) * 32 + c2 * 4 + 2*q)     << 10)] =
            fmaxf(x0, 0.f) + log1pf(expf(-fabsf(x0)));
        g_c2d[obase + ((size_t)((i1a + 1) * 32 + c2 * 4 + 2*q + 1) << 10)] =
            fmaxf(x1, 0.f) + log1pf(expf(-fabsf(x1)));
    }
}

// ---------------- 10) column maxes ----------------
__global__ void colmax_kernel() {
    __shared__ float red[8][32];
    int b = blockIdx.y;
    int j = blockIdx.x * 32 + threadIdx.x;
    const float* p = g_c2d + ((size_t)b << 20) + j;
    float m = -1e30f;
    for (int i = threadIdx.y; i < 1024; i += 8)
        m = fmaxf(m, p[(size_t)i << 10]);
    red[threadIdx.y][threadIdx.x] = m;
    __syncthreads();
    if (threadIdx.y == 0) {
#pragma unroll
        for (int s = 1; s < 8; s++) m = fmaxf(m, red[s][threadIdx.x]);
        g_cmax[b * 1024 + j] = m;
    }
}

// ---------------- 11) mutual-NN filter + softmax (rowmax fused) ----------------
__global__ __launch_bounds__(256) void softmax_kernel() {
    __shared__ float srow[1024];
    __shared__ float red[256];
    int row = blockIdx.x;
    int b = row >> 10;
    const float* p = g_c2d + (size_t)row * 1024;
    const float* cm = g_cmax + (b << 10);

    // pass 1: load row + raw row max
    float lraw = -1e30f;
    for (int j = threadIdx.x; j < 1024; j += 256) {
        float c = p[j];
        srow[j] = c;
        lraw = fmaxf(lraw, c);
    }
    red[threadIdx.x] = lraw; __syncthreads();
    for (int s = 128; s > 0; s >>= 1) {
        if (threadIdx.x < s) red[threadIdx.x] = fmaxf(red[threadIdx.x], red[threadIdx.x + s]);
        __syncthreads();
    }
    float rm = red[0]; if (rm == 0.f) rm = 1e-30f;
    float inv_rm = 1.0f / rm;
    __syncthreads();

    // pass 2: mutual-NN transform + softmax max
    float lmax = -1e30f;
    for (int j = threadIdx.x; j < 1024; j += 256) {
        float c = srow[j];
        float cmj = cm[j]; if (cmj == 0.f) cmj = 1e-30f;
        float t = c * (c * inv_rm) * (c / cmj) * 20.0f;
        srow[j] = t;
        lmax = fmaxf(lmax, t);
    }
    red[threadIdx.x] = lmax; __syncthreads();
    for (int s = 128; s > 0; s >>= 1) {
        if (threadIdx.x < s) red[threadIdx.x] = fmaxf(red[threadIdx.x], red[threadIdx.x + s]);
        __syncthreads();
    }
    float M = red[0];
    __syncthreads();

    float lsum = 0.f;
    for (int j = threadIdx.x; j < 1024; j += 256) {
        float e = expf(srow[j] - M);
        srow[j] = e; lsum += e;
    }
    red[threadIdx.x] = lsum; __syncthreads();
    for (int s = 128; s > 0; s >>= 1) {
        if (threadIdx.x < s) red[threadIdx.x] += red[threadIdx.x + s];
        __syncthreads();
    }
    float inv = 1.0f / red[0];
    float* a = g_attn + (size_t)row * 1024;
    for (int j = threadIdx.x; j < 1024; j += 256) a[j] = srow[j] * inv;
}

// ---------------- 12) out = v @ attn^T, f32x2 c-pairs, 128x64 tile ----------------
__global__ __launch_bounds__(256) void gemm_kernel(const float* __restrict__ v,
                                                   float* __restrict__ out) {
    __shared__ __align__(16) u64   Vs[16][68];
    __shared__ __align__(16) float As[16][68];
    int b = blockIdx.z;
    int m0 = blockIdx.x * 64;
    int c0 = blockIdx.y * 128;
    int tx = threadIdx.x & 15, ty = threadIdx.x >> 4;
    const float* vp = v + ((size_t)b * 512 + c0) * 1024;
    const float* ap = g_attn + ((size_t)b * 1024 + m0) * 1024;
    u64 acc[4][4];
#pragma unroll
    for (int i = 0; i < 4; i++)
#pragma unroll
        for (int j = 0; j < 4; j++) acc[i][j] = 0ull;

    for (int k0 = 0; k0 < 1024; k0 += 16) {
#pragma unroll
        for (int l = 0; l < 4; l++) {
            int e = threadIdx.x + l * 256;
            int cp = e >> 4, kk = e & 15;
            float v0 = vp[(size_t)(2*cp)   * 1024 + k0 + kk];
            float v1 = vp[(size_t)(2*cp+1) * 1024 + k0 + kk];
            Vs[kk][cp] = pk2(v0, v1);
            As[kk][cp] = ap[(size_t)cp * 1024 + k0 + kk];
        }
        __syncthreads();
#pragma unroll
        for (int kk = 0; kk < 16; kk++) {
            ulonglong2 va0 = *(const ulonglong2*)&Vs[kk][ty * 4];
            ulonglong2 va1 = *(const ulonglong2*)&Vs[kk][ty * 4 + 2];
            u64 rv[4] = {va0.x, va0.y, va1.x, va1.y};
            float4 rb = *(const float4*)&As[kk][tx * 4];
            u64 ra[4];
            ra[0] = pk2(rb.x, rb.x);
            ra[1] = pk2(rb.y, rb.y);
            ra[2] = pk2(rb.z, rb.z);
            ra[3] = pk2(rb.w, rb.w);
#pragma unroll
            for (int i = 0; i < 4; i++)
#pragma unroll
                for (int j = 0; j < 4; j++) fma2(acc[i][j], rv[i], ra[j]);
        }
        __syncthreads();
    }
    float* op = out + ((size_t)b * 512 + c0) * 1024 + m0;
#pragma unroll
    for (int i = 0; i < 4; i++) {
        float lo0, hi0, lo1, hi1, lo2, hi2, lo3, hi3;
        upk2(acc[i][0], lo0, hi0);
        upk2(acc[i][1], lo1, hi1);
        upk2(acc[i][2], lo2, hi2);
        upk2(acc[i][3], lo3, hi3);
        int c = ty * 8 + 2 * i;
        *(float4*)&op[(size_t)c * 1024 + tx * 4]       = make_float4(lo0, lo1, lo2, lo3);
        *(float4*)&op[(size_t)(c + 1) * 1024 + tx * 4] = make_float4(hi0, hi1, hi2, hi3);
    }
}

// ---------------- launcher ----------------
extern "C" void kernel_launch(void* const* d_in, const int* in_sizes, int n_in,
                              void* d_out, int out_size) {
    (void)in_sizes; (void)n_in; (void)out_size;
    const float* src = (const float*)d_in[0];
    const float* trg = (const float*)d_in[1];
    const float* v   = (const float*)d_in[2];
    const float* w0  = (const float*)d_in[3];
    const float* w1  = (const float*)d_in[4];
    const float* w2  = (const float*)d_in[5];
    const float* k6d = (const float*)d_in[6];
    const float* b6d = (const float*)d_in[7];
    const float* k4d = (const float*)d_in[8];
    const float* b4d = (const float*)d_in[9];
    float* out = (float*)d_out;

    cudaFuncSetAttribute(conv6d_kernel,
                         cudaFuncAttributeMaxDynamicSharedMemorySize, C6_SMEM);

    wtrans_kernel<<<dim3((COUT*CIN*9 + 255)/256, 3), 256>>>(w0, w1, w2);
    interp_feat_kernel<<<dim3((BB*CIN*529 + 255)/256, 3), 256>>>(src, 0);
    interp_feat_kernel<<<dim3((BB*CIN*529 + 255)/256, 3), 256>>>(trg, 1);
    conv2d_kernel<<<dim3(15, 2*BB, 4), 256>>>();
    reduce4_kernel<<<(int)(((size_t)6*SLOTPAD + 255)/256), 256>>>();
    norm_kernel<<<dim3((BB*529 + 7)/8, 6), 256>>>();
    corr_kernel<<<dim3(34, 34, 9*BB), dim3(16,16)>>>();
    interp4d_pair_kernel<<<dim3((BB*65536 + 255)/256, 9), 256>>>();
    conv6d_kernel<<<dim3(16, 9, BB), 256, C6_SMEM>>>(k6d);
    sigmax_kernel<<<(BB*65536 + 255)/256, 256>>>(b6d);
    up4d_kernel<<<(int)(((size_t)BB*1048576 + 255)/256), 256>>>();
    conv4d_kernel<<<dim3(8, 16, BB), 1024>>>(k4d, b4d);
    colmax_kernel<<<dim3(32, BB), dim3(32, 8)>>>();
    softmax_kernel<<<BB*1024, 256>>>();
    gemm_kernel<<<dim3(16, 4, BB), 256>>>(v, out);
}

// round 17
// speedup vs baseline: 1.0729x; 1.0729x over previous
#include <cuda_runtime.h>
#include <math.h>

#define BB   4
#define CIN  512
#define COUT 128
#define SLOTPAD 270848   // BB*COUT*529

typedef unsigned long long u64;

__device__ __forceinline__ u64 pk2(float lo, float hi) {
    u64 r; asm("mov.b64 %0, {%1, %2};" : "=l"(r) : "f"(lo), "f"(hi)); return r;
}
__device__ __forceinline__ void upk2(u64 v, float& lo, float& hi) {
    asm("mov.b64 {%0, %1}, %2;" : "=f"(lo), "=f"(hi) : "l"(v));
}
__device__ __forceinline__ void fma2(u64& d, u64 a, u64 b) {
    asm("fma.rn.f32x2 %0, %1, %2, %0;" : "+l"(d) : "l"(a), "l"(b));
}

// ---------------- static device scratch ----------------
__device__ float g_interp[2][1855488];
__device__ float g_part[4][6 * SLOTPAD];
__device__ float g_feat[6][SLOTPAD];
__device__ float g_norm[6][BB*529];
__device__ float g_pair[9][BB*529*529];
__device__ float g_corr6d[BB*9*65536];
__device__ float g_conv6d[BB*9*65536];
__device__ float g_max4[BB*65536];
__device__ float g_i32[(size_t)BB*1048576];
__device__ float g_c2d[(size_t)BB*1048576];
__device__ float g_cmax[BB*1024];
__device__ float g_attn[(size_t)BB*1048576];
__device__ float g_wT[3][CIN*9*COUT];

__device__ __forceinline__ void axisw(int o, float sc, int hi,
                                      int& i0, int& i1, float& w) {
    float f = (float)o * sc;
    int a = (int)f;
    if (a > hi) a = hi;
    w  = f - (float)a;
    i0 = a;
    i1 = (a + 1 < hi) ? a + 1 : hi;
}

// ---------------- 0) weight transpose [oc][ic*9] -> [ic*9][oc] ----------------
__global__ void wtrans_kernel(const float* __restrict__ w0,
                              const float* __restrict__ w1,
                              const float* __restrict__ w2) {
    int s = blockIdx.y;
    const float* w = (s == 0) ? w0 : ((s == 1) ? w1 : w2);
    int i = blockIdx.x * 256 + threadIdx.x;
    if (i >= COUT * CIN * 9) return;
    int oc = i / (CIN * 9);
    int r  = i % (CIN * 9);
    g_wT[s][(size_t)r * COUT + oc] = w[i];
}

// ---------------- 1) bilinear 16x16 -> sz x sz ----------------
__global__ void interp_feat_kernel(const float* __restrict__ in, int which) {
    int s = blockIdx.y;
    int sz = (s == 0) ? 11 : ((s == 1) ? 16 : 23);
    int off = (s == 0) ? 0 : ((s == 1) ? 247808 : 772096);
    int idx = blockIdx.x * 256 + threadIdx.x;
    int total = BB * CIN * sz * sz;
    if (idx >= total) return;
    int x  = idx % sz;
    int y  = (idx / sz) % sz;
    int bc = idx / (sz * sz);
    float sc = 15.0f / (float)(sz - 1);
    int y0, y1, x0, x1; float wy, wx;
    axisw(y, sc, 15, y0, y1, wy);
    axisw(x, sc, 15, x0, x1, wx);
    const float* p = in + (size_t)bc * 256;
    float v = (1.f - wy) * ((1.f - wx) * p[y0*16 + x0] + wx * p[y0*16 + x1])
            +        wy  * ((1.f - wx) * p[y1*16 + x0] + wx * p[y1*16 + x1]);
    g_interp[which][off + idx] = v;
}

// ---------------- 2) 3x3 conv 512->128 as f32x2 GEMM, ic split 4 ways ----------------
__global__ __launch_bounds__(256) void conv2d_kernel() {
    int t = blockIdx.x;   // 0..14
    int s, tile;
    if (t < 2)      { s = 0; tile = t; }
    else if (t < 6) { s = 1; tile = t - 2; }
    else            { s = 2; tile = t - 6; }
    int sz  = (s == 0) ? 11 : ((s == 1) ? 16 : 23);
    int off = (s == 0) ? 0  : ((s == 1) ? 247808 : 772096);
    int n2  = sz * sz;
    int which = blockIdx.y & 1;
    int b     = blockIdx.y >> 1;
    int chunk = blockIdx.z;
    int px0 = tile * 64;

    __shared__ __align__(16) float Ws[36 * 128];
    __shared__ __align__(16) float Xs[36 * 64];

    int tid = threadIdx.x;
    int ocg = tid >> 4;
    int pxg = tid & 15;

    int jj = tid & 63;
    int gg = tid >> 6;
    int gpx = px0 + jj;
    bool gvalid = (gpx < n2);
    int gy = 0, gx = 0;
    if (gvalid) { gy = gpx / sz; gx = gpx - gy * sz; }

    const float* inb = g_interp[which] + off + (size_t)b * CIN * n2;
    const float* wT  = g_wT[s];

    u64 acc[4][4];
#pragma unroll
    for (int i = 0; i < 4; i++)
#pragma unroll
        for (int j = 0; j < 4; j++) acc[i][j] = 0ull;

    int icBeg = chunk * 128;
    for (int ic0 = icBeg; ic0 < icBeg + 128; ic0 += 4) {
        const float* wsrc = wT + (size_t)(ic0 * 9) * COUT;
#pragma unroll
        for (int l = 0; l < 18; l++)
            Ws[tid + l * 256] = wsrc[tid + l * 256];
        {
            const float* ib = inb + (size_t)(ic0 + gg) * n2;
#pragma unroll
            for (int kk = 0; kk < 9; kk++) {
                int ky = kk / 3, kx = kk % 3;
                int yy = gy + ky - 1, xx = gx + kx - 1;
                float v = 0.f;
                if (gvalid && (unsigned)yy < (unsigned)sz && (unsigned)xx < (unsigned)sz)
                    v = ib[yy * sz + xx];
                Xs[(gg * 9 + kk) * 64 + jj] = v;
            }
        }
        __syncthreads();
#pragma unroll 6
        for (int r = 0; r < 36; r++) {
            const u64* wr = (const u64*)(Ws + r * 128) + ocg * 4;
            u64 w4[4];
            w4[0] = wr[0]; w4[1] = wr[1]; w4[2] = wr[2]; w4[3] = wr[3];
            const float* xr = Xs + r * 64 + pxg * 4;
            u64 xp[4];
#pragma unroll
            for (int i2 = 0; i2 < 4; i2++) { float xv = xr[i2]; xp[i2] = pk2(xv, xv); }
#pragma unroll
            for (int p2 = 0; p2 < 4; p2++)
#pragma unroll
                for (int i2 = 0; i2 < 4; i2++)
                    fma2(acc[p2][i2], w4[p2], xp[i2]);
        }
        __syncthreads();
    }

    int oc0 = ocg * 8;
    int slot = which * 3 + s;
    float* outp = g_part[chunk] + (size_t)slot * SLOTPAD + (size_t)b * COUT * n2;
#pragma unroll
    for (int p2 = 0; p2 < 4; p2++)
#pragma unroll
        for (int i2 = 0; i2 < 4; i2++) {
            float lo, hi;
            upk2(acc[p2][i2], lo, hi);
            int px = px0 + pxg * 4 + i2;
            if (px < n2) {
                outp[(size_t)(oc0 + 2*p2)     * n2 + px] = lo;
                outp[(size_t)(oc0 + 2*p2 + 1) * n2 + px] = hi;
            }
        }
}

// ---------------- 2b) reduce the 4 ic-chunks ----------------
__global__ void reduce4_kernel() {
    size_t i = (size_t)blockIdx.x * 256 + threadIdx.x;
    if (i >= (size_t)6 * SLOTPAD) return;
    (&g_feat[0][0])[i] = g_part[0][i] + g_part[1][i] + g_part[2][i] + g_part[3][i];
}

// ---------------- 3) per-pixel channel norms ----------------
__global__ void norm_kernel() {
    int slot = blockIdx.y;
    int s = slot % 3;
    int n2 = (s == 0) ? 121 : ((s == 1) ? 256 : 529);
    int rows = BB * n2;
    int wrp = blockIdx.x * 8 + (threadIdx.x >> 5);
    int lane = threadIdx.x & 31;
    if (wrp >= rows) return;
    int b = wrp / n2, n = wrp - b * n2;
    const float* f = g_feat[slot] + (size_t)b * COUT * n2 + n;
    float ssum = 0.f;
#pragma unroll
    for (int k = 0; k < 4; k++) {
        float v = f[(size_t)(lane + 32 * k) * n2];
        ssum += v * v;
    }
#pragma unroll
    for (int o = 16; o > 0; o >>= 1) ssum += __shfl_xor_sync(0xffffffffu, ssum, o);
    if (lane == 0) g_norm[slot][wrp] = sqrtf(ssum);
}

// ---------------- 4) normalized correlation GEMM, all 9 pairs fused ----------------
__global__ __launch_bounds__(256) void corr_kernel() {
    __shared__ float Ss[16][17];
    __shared__ float Ts[16][17];
    int z = blockIdx.z;
    int pair = z % 9, b = z / 9;
    int si = pair / 3, tj = pair % 3;
    int N = (si == 0) ? 121 : ((si == 1) ? 256 : 529);
    int M = (tj == 0) ? 121 : ((tj == 1) ? 256 : 529);
    int n0 = blockIdx.y * 16, m0 = blockIdx.x * 16;
    if (n0 >= N || m0 >= M) return;
    int tx = threadIdx.x, ty = threadIdx.y;
    const float* sp = g_feat[si]     + (size_t)b * COUT * N;
    const float* tp = g_feat[3 + tj] + (size_t)b * COUT * M;
    float acc = 0.f;
    for (int k0 = 0; k0 < COUT; k0 += 16) {
        int n = n0 + tx;
        Ss[ty][tx] = (n < N) ? sp[(size_t)(k0 + ty) * N + n] : 0.f;
        int m = m0 + tx;
        Ts[ty][tx] = (m < M) ? tp[(size_t)(k0 + ty) * M + m] : 0.f;
        __syncthreads();
#pragma unroll
        for (int kk = 0; kk < 16; kk++) acc += Ss[kk][ty] * Ts[kk][tx];
        __syncthreads();
    }
    int n = n0 + ty, m = m0 + tx;
    if (n < N && m < M) {
        float d = g_norm[si][b * N + n] * g_norm[3 + tj][b * M + m];
        g_pair[pair][(size_t)b * N * M + (size_t)n * M + m] = acc / d;
    }
}

// ---------------- 5) 4D tensor-product bilinear to 16^4 + clip, all 9 pairs ----------------
__global__ void interp4d_pair_kernel() {
    int pair = blockIdx.y;
    int si = pair / 3, tj = pair % 3;
    int ssi = (si == 0) ? 11 : ((si == 1) ? 16 : 23);
    int ssj = (tj == 0) ? 11 : ((tj == 1) ? 16 : 23);
    int idx = blockIdx.x * 256 + threadIdx.x;
    if (idx >= BB * 65536) return;
    int b = idx >> 16;
    int r = idx & 65535;
    int x2 = r & 15, y2 = (r >> 4) & 15, x1 = (r >> 8) & 15, y1 = r >> 12;
    float sc1 = (float)(ssi - 1) / 15.0f, sc2 = (float)(ssj - 1) / 15.0f;
    int a0, a1, e0, e1, c0, c1, d0, d1;
    float wa, we, wc, wd;
    axisw(y1, sc1, ssi - 1, a0, a1, wa);
    axisw(x1, sc1, ssi - 1, e0, e1, we);
    axisw(y2, sc2, ssj - 1, c0, c1, wc);
    axisw(x2, sc2, ssj - 1, d0, d1, wd);
    const float* p = g_pair[pair] + (size_t)b * ssi * ssi * ssj * ssj;
    int M = ssj * ssj;
    int AA[2] = {a0, a1}; float WA[2] = {1.f - wa, wa};
    int EE[2] = {e0, e1}; float WE[2] = {1.f - we, we};
    int CC[2] = {c0, c1}; float WC[2] = {1.f - wc, wc};
    int DD[2] = {d0, d1}; float WD[2] = {1.f - wd, wd};
    float v = 0.f;
#pragma unroll
    for (int ii = 0; ii < 2; ii++)
#pragma unroll
        for (int jj = 0; jj < 2; jj++) {
            const float* row = p + (size_t)(AA[ii] * ssi + EE[jj]) * M;
            float inner = WC[0] * (WD[0] * row[CC[0]*ssj + DD[0]] + WD[1] * row[CC[0]*ssj + DD[1]])
                        + WC[1] * (WD[0] * row[CC[1]*ssj + DD[0]] + WD[1] * row[CC[1]*ssj + DD[1]]);
            v += WA[ii] * WE[jj] * inner;
        }
    v = fmaxf(v, 0.f);
    g_corr6d[((size_t)(b * 9 + pair) << 16) + r] = v;
}

// ---------------- 6) 6D conv: z1-UNPAIRED, transposed slab, column fill, 3 blocks/SM ----------------
#define SST 22
__global__ __launch_bounds__(256, 3) void conv6d_kernel(const float* __restrict__ k6d) {
    __shared__ u64 skc2[640];
    __shared__ float slab[400 * SST];   // [(z3*20+z4)*22 + z2]
    int z1 = blockIdx.x;
    int p  = blockIdx.y;
    int b  = blockIdx.z;
    int a = p / 3, a2 = p % 3;
    int tid = threadIdx.x;
    int z4 = tid & 15, z3 = tid >> 4;

    u64 acc[8];
#pragma unroll
    for (int q = 0; q < 8; q++) acc[q] = 0ull;

    for (int da = 0; da < 3; da++) {
        int ap = a + da - 1; if ((unsigned)ap >= 3u) continue;
        for (int db = 0; db < 3; db++) {
            int bp = a2 + db - 1; if ((unsigned)bp >= 3u) continue;
            __syncthreads();
            for (int i = tid; i < 625; i += 256) {
                float v = k6d[(da * 3 + db) * 625 + i];
                skc2[i] = pk2(v, v);
            }
            const float* volbase = g_corr6d + (((size_t)b * 9 + ap * 3 + bp) << 16);
            for (int z1p = z1 - 2; z1p <= z1 + 2; z1p++) {
                if ((unsigned)z1p >= 16u) continue;
                int d1 = z1p - z1 + 2;
                const float* src = volbase + ((size_t)z1p << 12);
                __syncthreads();
                // column-major fill: one thread per (z3,z4) column
                for (int c = tid; c < 400; c += 256) {
                    int sz3 = c / 20, sz4 = c - sz3 * 20;
                    int z3p = sz3 - 2, z4p = sz4 - 2;
                    float* dst = slab + c * SST;
                    if ((unsigned)z3p < 16u && (unsigned)z4p < 16u) {
                        const float* s2p = src + (z3p << 4) + z4p;
                        dst[0] = 0.f; dst[1] = 0.f;
#pragma unroll
                        for (int z2 = 2; z2 < 18; z2++)
                            dst[z2] = s2p[(z2 - 2) << 8];
                        dst[18] = 0.f; dst[19] = 0.f;
                    } else {
#pragma unroll
                        for (int z2 = 0; z2 < 20; z2++) dst[z2] = 0.f;
                    }
                }
                __syncthreads();
                const u64* kk = skc2 + d1 * 125;
#pragma unroll 1
                for (int d3 = 0; d3 < 5; d3++) {
#pragma unroll 1
                    for (int d4 = 0; d4 < 5; d4++) {
                        const float* sp = slab + ((z3 + d3) * 20 + (z4 + d4)) * SST;
                        u64 pe[10];
#pragma unroll
                        for (int i = 0; i < 10; i++)
                            pe[i] = *(const u64*)(sp + 2 * i);
                        u64 po[9];
#pragma unroll
                        for (int i = 0; i < 9; i++) {
                            float l0, h0, l1, h1;
                            upk2(pe[i], l0, h0);
                            upk2(pe[i+1], l1, h1);
                            po[i] = pk2(h0, l1);
                        }
#pragma unroll
                        for (int d2 = 0; d2 < 5; d2++) {
                            u64 w2 = kk[d2 * 25 + d3 * 5 + d4];
                            if (d2 & 1) {
#pragma unroll
                                for (int q = 0; q < 8; q++) fma2(acc[q], w2, po[(d2 >> 1) + q]);
                            } else {
#pragma unroll
                                for (int q = 0; q < 8; q++) fma2(acc[q], w2, pe[(d2 >> 1) + q]);
                            }
                        }
                    }
                }
            }
        }
    }
    float* outp = g_conv6d + ((((size_t)b * 9 + a * 3 + a2) * 16 + z1) << 12);
#pragma unroll
    for (int q = 0; q < 8; q++) {
        float lo, hi;
        upk2(acc[q], lo, hi);
        outp[((2*q)   << 8) + (z3 << 4) + z4] = lo;
        outp[((2*q+1) << 8) + (z3 << 4) + z4] = hi;
    }
}

// ---------------- 7) max over 9, +bias, sigmoid ----------------
__global__ void sigmax_kernel(const float* __restrict__ b6) {
    int idx = blockIdx.x * 256 + threadIdx.x;
    if (idx >= BB * 65536) return;
    int b = idx >> 16; int r = idx & 65535;
    const float* p = g_conv6d + (((size_t)b * 9) << 16) + r;
    float m = p[0];
#pragma unroll
    for (int q = 1; q < 9; q++) m = fmaxf(m, p[(size_t)q << 16]);
    m += b6[0];
    g_max4[idx] = 1.f / (1.f + expf(-m));
}

// ---------------- 8) 4D bilinear 16^4 -> 32^4 ----------------
__global__ void up4d_kernel() {
    size_t idx = (size_t)blockIdx.x * 256 + threadIdx.x;
    if (idx >= (size_t)BB * 1048576) return;
    int b = (int)(idx >> 20);
    int r = (int)(idx & 1048575);
    int x2 = r & 31, y2 = (r >> 5) & 31, x1 = (r >> 10) & 31, y1 = r >> 15;
    const float sc = 15.0f / 31.0f;
    int a0, a1, e0, e1, c0, c1, d0, d1; float wa, we, wc, wd;
    axisw(y1, sc, 15, a0, a1, wa);
    axisw(x1, sc, 15, e0, e1, we);
    axisw(y2, sc, 15, c0, c1, wc);
    axisw(x2, sc, 15, d0, d1, wd);
    const float* p = g_max4 + ((size_t)b << 16);
    int AA[2] = {a0, a1}; float WA[2] = {1.f - wa, wa};
    int EE[2] = {e0, e1}; float WE[2] = {1.f - we, we};
    int CC[2] = {c0, c1}; float WC[2] = {1.f - wc, wc};
    int DD[2] = {d0, d1}; float WD[2] = {1.f - wd, wd};
    float v = 0.f;
#pragma unroll
    for (int ii = 0; ii < 2; ii++)
#pragma unroll
        for (int jj = 0; jj < 2; jj++) {
            const float* row = p + ((AA[ii] * 16 + EE[jj]) << 8);
            float inner = WC[0] * (WD[0] * row[(CC[0] << 4) + DD[0]] + WD[1] * row[(CC[0] << 4) + DD[1]])
                        + WC[1] * (WD[0] * row[(CC[1] << 4) + DD[0]] + WD[1] * row[(CC[1] << 4) + DD[1]]);
            v += WA[ii] * WE[jj] * inner;
        }
    g_i32[idx] = v;
}

// ---------------- 9) 4D conv 5^4, i1-paired + f32x2, column fill ----------------
__global__ __launch_bounds__(1024) void conv4d_kernel(const float* __restrict__ k4d,
                                                      const float* __restrict__ b4d) {
    __shared__ float skc[640];
    __shared__ float slab[10368];     // 8*36*36, [s2*1296 + s3*36 + s4]
    int c2  = blockIdx.x;
    int i1a = blockIdx.y * 2;
    int b   = blockIdx.z;
    int tid = threadIdx.x;
    int i4 = tid & 31, i3 = tid >> 5;

    for (int i = tid; i < 625; i += 1024) skc[i] = k4d[i];

    u64 accA[2], accB[2];
#pragma unroll
    for (int q = 0; q < 2; q++) { accA[q] = 0ull; accB[q] = 0ull; }

    const float* base = g_i32 + ((size_t)b << 20);
    for (int i1p = i1a - 2; i1p <= i1a + 3; i1p++) {
        if ((unsigned)i1p >= 32u) continue;
        int d1a = i1p - i1a + 2;
        int d1b = d1a - 1;
        bool va = (unsigned)d1a < 5u;
        bool vb = (unsigned)d1b < 5u;
        const float* src = base + ((size_t)i1p << 15);
        __syncthreads();
        for (int c = tid; c < 1296; c += 1024) {
            int s3 = c / 36, s4 = c - s3 * 36;
            int i3p = s3 - 2, i4p = s4 - 2;
            bool v34 = ((unsigned)i3p < 32u) && ((unsigned)i4p < 32u);
            const float* sp2 = src + (i3p << 5) + i4p;
#pragma unroll
            for (int s2 = 0; s2 < 8; s2++) {
                int i2p = c2 * 4 + s2 - 2;
                float vv = 0.f;
                if (v34 && (unsigned)i2p < 32u) vv = sp2[(size_t)i2p << 10];
                slab[s2 * 1296 + c] = vv;
            }
        }
        __syncthreads();
        const float* kA = skc + d1a * 125;
        const float* kB = skc + d1b * 125;
#pragma unroll 1
        for (int d3 = 0; d3 < 5; d3++) {
#pragma unroll 1
            for (int d4 = 0; d4 < 5; d4++) {
                float pvz[8];
                const float* sp = slab + (i3 + d3) * 36 + (i4 + d4);
#pragma unroll
                for (int s = 0; s < 8; s++) pvz[s] = sp[s * 1296];
                u64 pe[4], po[3];
#pragma unroll
                for (int i = 0; i < 4; i++) pe[i] = pk2(pvz[2*i], pvz[2*i+1]);
#pragma unroll
                for (int i = 0; i < 3; i++) po[i] = pk2(pvz[2*i+1], pvz[2*i+2]);
                if (va) {
#pragma unroll
                    for (int d2 = 0; d2 < 5; d2++) {
                        float w = kA[d2 * 25 + d3 * 5 + d4];
                        u64 w2 = pk2(w, w);
                        if (d2 & 1) {
#pragma unroll
                            for (int q = 0; q < 2; q++) fma2(accA[q], w2, po[(d2 >> 1) + q]);
                        } else {
#pragma unroll
                            for (int q = 0; q < 2; q++) fma2(accA[q], w2, pe[(d2 >> 1) + q]);
                        }
                    }
                }
                if (vb) {
#pragma unroll
                    for (int d2 = 0; d2 < 5; d2++) {
                        float w = kB[d2 * 25 + d3 * 5 + d4];
                        u64 w2 = pk2(w, w);
                        if (d2 & 1) {
#pragma unroll
                            for (int q = 0; q < 2; q++) fma2(accB[q], w2, po[(d2 >> 1) + q]);
                        } else {
#pragma unroll
                            for (int q = 0; q < 2; q++) fma2(accB[q], w2, pe[(d2 >> 1) + q]);
                        }
                    }
                }
            }
        }
    }
    float bb = b4d[0];
    size_t obase = ((size_t)b << 20) + i3 * 32 + i4;
#pragma unroll
    for (int q = 0; q < 2; q++) {
        float lo, hi;
        upk2(accA[q], lo, hi);
        float x0 = lo + bb, x1 = hi + bb;
        g_c2d[obase + ((size_t)(i1a * 32 + c2 * 4 + 2*q)     << 10)] =
            fmaxf(x0, 0.f) + log1pf(expf(-fabsf(x0)));
        g_c2d[obase + ((size_t)(i1a * 32 + c2 * 4 + 2*q + 1) << 10)] =
            fmaxf(x1, 0.f) + log1pf(expf(-fabsf(x1)));
        upk2(accB[q], lo, hi);
        x0 = lo + bb; x1 = hi + bb;
        g_c2d[obase + ((size_t)((i1a + 1) * 32 + c2 * 4 + 2*q)     << 10)] =
            fmaxf(x0, 0.f) + log1pf(expf(-fabsf(x0)));
        g_c2d[obase + ((size_t)((i1a + 1) * 32 + c2 * 4 + 2*q + 1) << 10)] =
            fmaxf(x1, 0.f) + log1pf(expf(-fabsf(x1)));
    }
}

// ---------------- 10) column maxes ----------------
__global__ void colmax_kernel() {
    __shared__ float red[8][32];
    int b = blockIdx.y;
    int j = blockIdx.x * 32 + threadIdx.x;
    const float* p = g_c2d + ((size_t)b << 20) + j;
    float m = -1e30f;
    for (int i = threadIdx.y; i < 1024; i += 8)
        m = fmaxf(m, p[(size_t)i << 10]);
    red[threadIdx.y][threadIdx.x] = m;
    __syncthreads();
    if (threadIdx.y == 0) {
#pragma unroll
        for (int s = 1; s < 8; s++) m = fmaxf(m, red[s][threadIdx.x]);
        g_cmax[b * 1024 + j] = m;
    }
}

// ---------------- 11) mutual-NN filter + softmax (rowmax fused) ----------------
__global__ __launch_bounds__(256) void softmax_kernel() {
    __shared__ float srow[1024];
    __shared__ float red[256];
    int row = blockIdx.x;
    int b = row >> 10;
    const float* p = g_c2d + (size_t)row * 1024;
    const float* cm = g_cmax + (b << 10);

    float lraw = -1e30f;
    for (int j = threadIdx.x; j < 1024; j += 256) {
        float c = p[j];
        srow[j] = c;
        lraw = fmaxf(lraw, c);
    }
    red[threadIdx.x] = lraw; __syncthreads();
    for (int s = 128; s > 0; s >>= 1) {
        if (threadIdx.x < s) red[threadIdx.x] = fmaxf(red[threadIdx.x], red[threadIdx.x + s]);
        __syncthreads();
    }
    float rm = red[0]; if (rm == 0.f) rm = 1e-30f;
    float inv_rm = 1.0f / rm;
    __syncthreads();

    float lmax = -1e30f;
    for (int j = threadIdx.x; j < 1024; j += 256) {
        float c = srow[j];
        float cmj = cm[j]; if (cmj == 0.f) cmj = 1e-30f;
        float t = c * (c * inv_rm) * (c / cmj) * 20.0f;
        srow[j] = t;
        lmax = fmaxf(lmax, t);
    }
    red[threadIdx.x] = lmax; __syncthreads();
    for (int s = 128; s > 0; s >>= 1) {
        if (threadIdx.x < s) red[threadIdx.x] = fmaxf(red[threadIdx.x], red[threadIdx.x + s]);
        __syncthreads();
    }
    float M = red[0];
    __syncthreads();

    float lsum = 0.f;
    for (int j = threadIdx.x; j < 1024; j += 256) {
        float e = expf(srow[j] - M);
        srow[j] = e; lsum += e;
    }
    red[threadIdx.x] = lsum; __syncthreads();
    for (int s = 128; s > 0; s >>= 1) {
        if (threadIdx.x < s) red[threadIdx.x] += red[threadIdx.x + s];
        __syncthreads();
    }
    float inv = 1.0f / red[0];
    float* a = g_attn + (size_t)row * 1024;
    for (int j = threadIdx.x; j < 1024; j += 256) a[j] = srow[j] * inv;
}

// ---------------- 12) out = v @ attn^T, f32x2 c-pairs, 128x64 tile ----------------
__global__ __launch_bounds__(256) void gemm_kernel(const float* __restrict__ v,
                                                   float* __restrict__ out) {
    __shared__ __align__(16) u64   Vs[16][68];
    __shared__ __align__(16) float As[16][68];
    int b = blockIdx.z;
    int m0 = blockIdx.x * 64;
    int c0 = blockIdx.y * 128;
    int tx = threadIdx.x & 15, ty = threadIdx.x >> 4;
    const float* vp = v + ((size_t)b * 512 + c0) * 1024;
    const float* ap = g_attn + ((size_t)b * 1024 + m0) * 1024;
    u64 acc[4][4];
#pragma unroll
    for (int i = 0; i < 4; i++)
#pragma unroll
        for (int j = 0; j < 4; j++) acc[i][j] = 0ull;

    for (int k0 = 0; k0 < 1024; k0 += 16) {
#pragma unroll
        for (int l = 0; l < 4; l++) {
            int e = threadIdx.x + l * 256;
            int cp = e >> 4, kk = e & 15;
            float v0 = vp[(size_t)(2*cp)   * 1024 + k0 + kk];
            float v1 = vp[(size_t)(2*cp+1) * 1024 + k0 + kk];
            Vs[kk][cp] = pk2(v0, v1);
            As[kk][cp] = ap[(size_t)cp * 1024 + k0 + kk];
        }
        __syncthreads();
#pragma unroll
        for (int kk = 0; kk < 16; kk++) {
            ulonglong2 va0 = *(const ulonglong2*)&Vs[kk][ty * 4];
            ulonglong2 va1 = *(const ulonglong2*)&Vs[kk][ty * 4 + 2];
            u64 rv[4] = {va0.x, va0.y, va1.x, va1.y};
            float4 rb = *(const float4*)&As[kk][tx * 4];
            u64 ra[4];
            ra[0] = pk2(rb.x, rb.x);
            ra[1] = pk2(rb.y, rb.y);
            ra[2] = pk2(rb.z, rb.z);
            ra[3] = pk2(rb.w, rb.w);
#pragma unroll
            for (int i = 0; i < 4; i++)
#pragma unroll
                for (int j = 0; j < 4; j++) fma2(acc[i][j], rv[i], ra[j]);
        }
        __syncthreads();
    }
    float* op = out + ((size_t)b * 512 + c0) * 1024 + m0;
#pragma unroll
    for (int i = 0; i < 4; i++) {
        float lo0, hi0, lo1, hi1, lo2, hi2, lo3, hi3;
        upk2(acc[i][0], lo0, hi0);
        upk2(acc[i][1], lo1, hi1);
        upk2(acc[i][2], lo2, hi2);
        upk2(acc[i][3], lo3, hi3);
        int c = ty * 8 + 2 * i;
        *(float4*)&op[(size_t)c * 1024 + tx * 4]       = make_float4(lo0, lo1, lo2, lo3);
        *(float4*)&op[(size_t)(c + 1) * 1024 + tx * 4] = make_float4(hi0, hi1, hi2, hi3);
    }
}

// ---------------- launcher ----------------
extern "C" void kernel_launch(void* const* d_in, const int* in_sizes, int n_in,
                              void* d_out, int out_size) {
    (void)in_sizes; (void)n_in; (void)out_size;
    const float* src = (const float*)d_in[0];
    const float* trg = (const float*)d_in[1];
    const float* v   = (const float*)d_in[2];
    const float* w0  = (const float*)d_in[3];
    const float* w1  = (const float*)d_in[4];
    const float* w2  = (const float*)d_in[5];
    const float* k6d = (const float*)d_in[6];
    const float* b6d = (const float*)d_in[7];
    const float* k4d = (const float*)d_in[8];
    const float* b4d = (const float*)d_in[9];
    float* out = (float*)d_out;

    wtrans_kernel<<<dim3((COUT*CIN*9 + 255)/256, 3), 256>>>(w0, w1, w2);
    interp_feat_kernel<<<dim3((BB*CIN*529 + 255)/256, 3), 256>>>(src, 0);
    interp_feat_kernel<<<dim3((BB*CIN*529 + 255)/256, 3), 256>>>(trg, 1);
    conv2d_kernel<<<dim3(15, 2*BB, 4), 256>>>();
    reduce4_kernel<<<(int)(((size_t)6*SLOTPAD + 255)/256), 256>>>();
    norm_kernel<<<dim3((BB*529 + 7)/8, 6), 256>>>();
    corr_kernel<<<dim3(34, 34, 9*BB), dim3(16,16)>>>();
    interp4d_pair_kernel<<<dim3((BB*65536 + 255)/256, 9), 256>>>();
    conv6d_kernel<<<dim3(16, 9, BB), 256>>>(k6d);
    sigmax_kernel<<<(BB*65536 + 255)/256, 256>>>(b6d);
    up4d_kernel<<<(int)(((size_t)BB*1048576 + 255)/256), 256>>>();
    conv4d_kernel<<<dim3(8, 16, BB), 1024>>>(k4d, b4d);
    colmax_kernel<<<dim3(32, BB), dim3(32, 8)>>>();
    softmax_kernel<<<BB*1024, 256>>>();
    gemm_kernel<<<dim3(16, 4, BB), 256>>>(v, out);
}